// round 3
// baseline (speedup 1.0000x reference)
#include <cuda_runtime.h>
#include <cuda_bf16.h>
#include <math.h>

// SetConv1dDecoder: out[b,m,c] = sum_n exp(-0.5*(x[b,m]-xz[n])^2 / scale^2) * z[b,c,n]
// Banded: weight = exp(-didx^2/8) in grid steps -> 32-point window suffices (<1e-9 rel).
// R3: smem-tiled. CTA = (batch, 64-pt grid segment). z tile staged in smem once,
// targets binned by window start via warp-aggregated compaction, then warp-per-target
// compute from smem (conflict-free LDS.128: row stride 100 floats == 4 mod 32).

#define WIN      32
#define SEG      64
#define TCOLS    (SEG + WIN)   // 96
#define TSTRIDE  100           // floats; 100 % 32 == 4 -> phase-conflict-free LDS.128
#define NTHREADS 256

__global__ void __launch_bounds__(NTHREADS) setconv_tiled_c16(
        const float* __restrict__ xz,
        const float* __restrict__ x,
        const float* __restrict__ z,
        const float* __restrict__ log_scale,
        float* __restrict__ out,
        int B, int M, int N, int nseg, int out_off)
{
    __shared__ __align__(16) float tile[16 * TSTRIDE];
    __shared__ int list[4096];      // worst-case: all targets in one segment
    __shared__ int count;

    const int tid  = threadIdx.x;
    const int lane = tid & 31;
    const int b    = blockIdx.x / nseg;
    const int seg  = blockIdx.x % nseg;
    const int s0   = seg * SEG;

    // tuple head: copy xz (grid-strided over all CTAs)
    for (int i = blockIdx.x * NTHREADS + tid; i < out_off; i += gridDim.x * NTHREADS)
        out[i] = xz[i];

    if (tid == 0) count = 0;

    const float ls       = *log_scale;
    const float alpha    = 0.5f * __expf(-2.0f * ls);
    const float xz0      = xz[0];
    const float step     = xz[1] - xz0;
    const float inv_step = 1.0f / step;

    // stage z tile: rows = 16 channels, cols = [s0, s0+96) clipped to N
    const float* zb = z + (size_t)b * 16 * N;
    #pragma unroll 2
    for (int i = tid; i < 16 * TCOLS; i += NTHREADS) {
        int c   = i / TCOLS;
        int col = i - c * TCOLS;
        if (s0 + col < N)
            tile[c * TSTRIDE + col] = zb[(size_t)c * N + s0 + col];
    }
    __syncthreads();   // tile ready + count initialized

    // scan all M targets of this batch; bin those whose window starts in [s0, s0+SEG)
    const float* xb = x + (size_t)b * M;
    for (int t0 = 0; t0 < M; t0 += NTHREADS) {
        int  t    = t0 + tid;
        bool mine = false;
        if (t < M) {
            float xv  = xb[t];
            int   idx = (int)floorf((xv - xz0) * inv_step);
            int   i0  = (idx - (WIN / 2 - 1)) & ~3;
            i0 = min(max(i0, 0), N - WIN);
            mine = (i0 >= s0) && (i0 < s0 + SEG);
        }
        unsigned mask = __ballot_sync(0xffffffffu, mine);
        if (mine) {
            int leader = __ffs(mask) - 1;
            int rank   = __popc(mask & ((1u << lane) - 1u));
            int base   = 0;
            if (lane == leader) base = atomicAdd(&count, __popc(mask));
            base = __shfl_sync(mask, base, leader);
            list[base + rank] = t;
        }
    }
    __syncthreads();

    // process: one warp per binned target, all data from smem
    const int cnt = count;
    const int wid = tid >> 5;
    const int c   = lane & 15;
    const int h   = lane >> 4;

    for (int j = wid; j < cnt; j += NTHREADS / 32) {
        int   t   = list[j];
        float xv  = xb[t];
        int   idx = (int)floorf((xv - xz0) * inv_step);
        int   i0  = (idx - (WIN / 2 - 1)) & ~3;
        i0 = min(max(i0, 0), N - WIN);
        const int li0 = i0 - s0;                  // in [0, SEG), mult of 4

        // lane k holds weight for window point k
        float gx = xz0 + (float)(i0 + lane) * step;
        float d  = xv - gx;
        float w  = __expf(-alpha * d * d);

        const float4* p = (const float4*)&tile[c * TSTRIDE + li0 + h * 16];
        float4 v0 = p[0], v1 = p[1], v2 = p[2], v3 = p[3];

        const int hb = h << 4;
        float s = 0.0f;
        s += v0.x * __shfl_sync(0xffffffffu, w, hb + 0);
        s += v0.y * __shfl_sync(0xffffffffu, w, hb + 1);
        s += v0.z * __shfl_sync(0xffffffffu, w, hb + 2);
        s += v0.w * __shfl_sync(0xffffffffu, w, hb + 3);
        s += v1.x * __shfl_sync(0xffffffffu, w, hb + 4);
        s += v1.y * __shfl_sync(0xffffffffu, w, hb + 5);
        s += v1.z * __shfl_sync(0xffffffffu, w, hb + 6);
        s += v1.w * __shfl_sync(0xffffffffu, w, hb + 7);
        s += v2.x * __shfl_sync(0xffffffffu, w, hb + 8);
        s += v2.y * __shfl_sync(0xffffffffu, w, hb + 9);
        s += v2.z * __shfl_sync(0xffffffffu, w, hb + 10);
        s += v2.w * __shfl_sync(0xffffffffu, w, hb + 11);
        s += v3.x * __shfl_sync(0xffffffffu, w, hb + 12);
        s += v3.y * __shfl_sync(0xffffffffu, w, hb + 13);
        s += v3.z * __shfl_sync(0xffffffffu, w, hb + 14);
        s += v3.w * __shfl_sync(0xffffffffu, w, hb + 15);

        s += __shfl_xor_sync(0xffffffffu, s, 16);  // combine window halves

        if (h == 0)
            out[out_off + ((size_t)b * M + t) * 16 + c] = s;  // 64B coalesced
    }
}

// Generic fallback for C != 16.
__global__ void setconv_generic_kernel(const float* __restrict__ xz,
                                       const float* __restrict__ x,
                                       const float* __restrict__ z,
                                       const float* __restrict__ log_scale,
                                       float* __restrict__ out,
                                       int BM, int M, int C, int N, int out_off)
{
    const int tid = blockIdx.x * blockDim.x + threadIdx.x;
    if (tid < out_off) out[tid] = xz[tid];
    if (tid >= BM) return;

    const int b = tid / M;
    const float ls       = *log_scale;
    const float alpha    = 0.5f * __expf(-2.0f * ls);
    const float xz0      = xz[0];
    const float step     = xz[1] - xz[0];
    const float inv_step = 1.0f / step;
    const float xv = x[tid];

    int idx = (int)floorf((xv - xz0) * inv_step);
    int i0  = idx - (WIN / 2 - 1);
    i0 = min(max(i0, 0), N - WIN);

    const float* zb = z + (size_t)b * C * N;

    float w[WIN];
#pragma unroll
    for (int k = 0; k < WIN; ++k) {
        float gx = xz0 + (float)(i0 + k) * step;
        float d  = xv - gx;
        w[k] = __expf(-alpha * d * d);
    }

    for (int c = 0; c < C; ++c) {
        const float* zp = zb + (size_t)c * N + i0;
        float s = 0.0f;
#pragma unroll
        for (int k = 0; k < WIN; ++k) s += w[k] * zp[k];
        out[out_off + (size_t)tid * C + c] = s;
    }
}

extern "C" void kernel_launch(void* const* d_in, const int* in_sizes, int n_in,
                              void* d_out, int out_size)
{
    const float* xz = (const float*)d_in[0];   // [N,1]
    const float* x  = (const float*)d_in[1];   // [B,M,1]
    const float* z  = (const float*)d_in[2];   // [B,C,N]
    const float* ls = (const float*)d_in[3];   // scalar

    const int N   = in_sizes[0];
    const int BM  = in_sizes[1];
    const int BCN = in_sizes[2];
    const int BC  = BCN / N;

    int C, out_off;
    if ((out_size - N) > 0 && (out_size - N) % BM == 0 &&
        (BC % ((out_size - N) / BM)) == 0) {
        C = (out_size - N) / BM;   // tuple output: [xz | out]
        out_off = N;
    } else {
        C = out_size / BM;         // out-only
        out_off = 0;
    }
    const int B = BC / C;
    const int M = BM / B;

    float* out = (float*)d_out;

    if (C == 16 && M <= 4096 && N >= WIN) {
        const int nseg   = (N + SEG - 1) / SEG;
        const int blocks = B * nseg;
        setconv_tiled_c16<<<blocks, NTHREADS>>>(xz, x, z, ls, out, B, M, N, nseg, out_off);
    } else {
        const int threads = 128;
        const int work    = (BM > out_off) ? BM : out_off;
        const int blocks  = (work + threads - 1) / threads;
        setconv_generic_kernel<<<blocks, threads>>>(xz, x, z, ls, out, BM, M, C, N, out_off);
    }
}